// round 4
// baseline (speedup 1.0000x reference)
#include <cuda_runtime.h>

#define Bg 256
#define Nn 128
#define Dd 128
#define Ll 32
#define Ee 262144
#define BNt 32768
#define Pp 8128
#define MW 256   // mask words per graph (254 used, padded)

__device__ float    g_agg[BNt * Dd];     // 16 MB scatter accumulator
__device__ float    g_z[BNt * Ll];       // 4 MB latents
__device__ unsigned g_mask[Bg * MW];     // per-graph edge bitmask
__device__ float    g_acc[2];            // [0]=sum log_probs, [1]=sum kls
__device__ int      g_is64;              // edge_index dtype flag

// ---------------------------------------------------------------------------
// init: zero accumulators + detect edge_index dtype (int64 vs int32)
// ---------------------------------------------------------------------------
__global__ void k_init(const void* ei) {
    int i = blockIdx.x * blockDim.x + threadIdx.x;
    int stride = gridDim.x * blockDim.x;
    float4 z4 = make_float4(0.f, 0.f, 0.f, 0.f);
    for (int j = i; j < BNt * Dd / 4; j += stride) ((float4*)g_agg)[j] = z4;
    for (int j = i; j < Bg * MW; j += stride) g_mask[j] = 0u;
    if (i < 2) g_acc[i] = 0.f;
    if (i == 0) {
        // int64 little-endian: hi word of every entry is 0 (values < 2^31).
        // int32 data: these positions are src node ids, ~never all zero.
        const int* e32 = (const int*)ei;
        int all0 = 1;
        #pragma unroll
        for (int t = 0; t < 32; t++) all0 &= (e32[2 * t + 1] == 0);
        g_is64 = all0;
    }
}

// ---------------------------------------------------------------------------
// edge scatter: agg[dst] += x[src], agg[src] += x[dst]; set pair bit
// one warp per edge, red.global.add.v4.f32
// ---------------------------------------------------------------------------
__global__ void k_scatter(const float* __restrict__ x, const void* __restrict__ ei) {
    int e = (blockIdx.x * blockDim.x + threadIdx.x) >> 5;
    int lane = threadIdx.x & 31;
    if (e >= Ee) return;
    int s, d;
    if (g_is64) {
        s = (int)((const long long*)ei)[e];
        d = (int)((const long long*)ei)[Ee + e];
    } else {
        s = ((const int*)ei)[e];
        d = ((const int*)ei)[Ee + e];
    }
    const float4* xv = (const float4*)x;
    float4 vs = xv[s * (Dd / 4) + lane];
    float4 vd = xv[d * (Dd / 4) + lane];
    float* ad = &g_agg[d * Dd + lane * 4];
    float* as = &g_agg[s * Dd + lane * 4];
    asm volatile("red.global.add.v4.f32 [%0], {%1,%2,%3,%4};"
                 :: "l"(ad), "f"(vs.x), "f"(vs.y), "f"(vs.z), "f"(vs.w) : "memory");
    asm volatile("red.global.add.v4.f32 [%0], {%1,%2,%3,%4};"
                 :: "l"(as), "f"(vd.x), "f"(vd.y), "f"(vd.z), "f"(vd.w) : "memory");
    if (lane == 0) {
        int li = s & (Nn - 1), lj = d & (Nn - 1), b = s >> 7;
        int p = li * (2 * Nn - li - 1) / 2 + (lj - li - 1);
        atomicOr(&g_mask[b * MW + (p >> 5)], 1u << (p & 31));
    }
}

// ---------------------------------------------------------------------------
// block reduction helper
// ---------------------------------------------------------------------------
__device__ __forceinline__ float block_reduce(float v) {
    __shared__ float sred[8];
    int lane = threadIdx.x & 31, w = threadIdx.x >> 5;
    #pragma unroll
    for (int o = 16; o; o >>= 1) v += __shfl_down_sync(0xffffffffu, v, o);
    if (lane == 0) sred[w] = v;
    __syncthreads();
    v = (threadIdx.x < 8) ? sred[threadIdx.x] : 0.f;
    if (w == 0) {
        #pragma unroll
        for (int o = 4; o; o >>= 1) v += __shfl_down_sync(0xffu, v, o);
    }
    return v;  // valid in thread 0
}

// ---------------------------------------------------------------------------
// fused encoder: h = relu((x+agg)@W1 + b1); mu/ls GEMMs; z, KL
// CTA = 64 rows; dynamic smem: W1 (64KB) | T (32KB) | H (32KB)
// ---------------------------------------------------------------------------
__global__ void k_enc(const float* __restrict__ x, const float* __restrict__ W1,
                      const float* __restrict__ b1, const float* __restrict__ Wmu,
                      const float* __restrict__ bmu, const float* __restrict__ Wls,
                      const float* __restrict__ bls, const float* __restrict__ eps) {
    extern __shared__ float sm[];
    float* shW = sm;            // 16384 floats
    float* shT = sm + 16384;    // 8192 floats
    float* shH = sm + 24576;    // 8192 floats
    const int tid = threadIdx.x;
    const int r0 = blockIdx.x * 64;

    for (int i = tid; i < 4096; i += 256) ((float4*)shW)[i] = ((const float4*)W1)[i];
    for (int i = tid; i < 2048; i += 256) {
        float4 a = ((const float4*)(x + (size_t)r0 * Dd))[i];
        float4 g = ((const float4*)(g_agg + (size_t)r0 * Dd))[i];
        a.x += g.x; a.y += g.y; a.z += g.z; a.w += g.w;
        ((float4*)shT)[i] = a;
    }
    __syncthreads();

    // phase 1: h tile (64x128), thread = 8 rows x 4 cols
    {
        const int c  = (tid & 31) * 4;
        const int rg = (tid >> 5) * 8;
        float acc[8][4];
        #pragma unroll
        for (int i = 0; i < 8; i++) { acc[i][0]=0.f; acc[i][1]=0.f; acc[i][2]=0.f; acc[i][3]=0.f; }
        for (int k = 0; k < 128; k++) {
            float4 w = *(const float4*)&shW[k * 128 + c];
            #pragma unroll
            for (int i = 0; i < 8; i++) {
                float a = shT[(rg + i) * 128 + k];
                acc[i][0] += a * w.x; acc[i][1] += a * w.y;
                acc[i][2] += a * w.z; acc[i][3] += a * w.w;
            }
        }
        float4 bb = *(const float4*)(b1 + c);
        #pragma unroll
        for (int i = 0; i < 8; i++) {
            float4 h;
            h.x = fmaxf(acc[i][0] + bb.x, 0.f);
            h.y = fmaxf(acc[i][1] + bb.y, 0.f);
            h.z = fmaxf(acc[i][2] + bb.z, 0.f);
            h.w = fmaxf(acc[i][3] + bb.w, 0.f);
            *(float4*)&shH[(rg + i) * 128 + c] = h;
        }
    }
    __syncthreads();

    // reuse W1 region for Wmu | Wls
    for (int i = tid; i < 1024; i += 256) {
        ((float4*)shW)[i]          = ((const float4*)Wmu)[i];
        ((float4*)(shW + 4096))[i] = ((const float4*)Wls)[i];
    }
    __syncthreads();

    // phase 2: mu/ls, z, KL; thread = 8 rows x 1 latent
    float klp = 0.f;
    {
        const int l  = tid & 31;
        const int rg = (tid >> 5) * 8;
        float mu[8], ls[8];
        #pragma unroll
        for (int i = 0; i < 8; i++) { mu[i] = 0.f; ls[i] = 0.f; }
        for (int k = 0; k < 128; k++) {
            float wm = shW[k * 32 + l];
            float wl = shW[4096 + k * 32 + l];
            #pragma unroll
            for (int i = 0; i < 8; i++) {
                float hv = shH[(rg + i) * 128 + k];
                mu[i] += hv * wm; ls[i] += hv * wl;
            }
        }
        float bm = bmu[l], bl = bls[l];
        #pragma unroll
        for (int i = 0; i < 8; i++) {
            int row = r0 + rg + i;
            float m  = mu[i] + bm;
            float s  = ls[i] + bl;
            float st = __expf(s);
            g_z[row * Ll + l] = m + st * eps[row * Ll + l];
            klp += 0.5f * (st * st + m * m - 1.f - 2.f * s);
        }
    }
    float tot = block_reduce(klp);
    if (tid == 0) atomicAdd(&g_acc[1], tot);
}

// ---------------------------------------------------------------------------
// decoder: per graph, gram = Z Z^T, upper-triangle bernoulli log-prob
// ---------------------------------------------------------------------------
__global__ void k_dec() {
    __shared__ float    shZ[128 * 33];
    __shared__ unsigned shM[MW];
    const int tid = threadIdx.x;
    const int b = blockIdx.x;
    for (int i = tid; i < 4096; i += 256)
        shZ[(i >> 5) * 33 + (i & 31)] = g_z[b * 4096 + i];
    for (int i = tid; i < MW; i += 256) shM[i] = g_mask[b * MW + i];
    __syncthreads();

    const int tx = tid & 15, ty = tid >> 4;
    const int r0 = ty * 8, c0 = tx * 8;
    float acc[8][8];
    #pragma unroll
    for (int i = 0; i < 8; i++)
        #pragma unroll
        for (int j = 0; j < 8; j++) acc[i][j] = 0.f;

    for (int k = 0; k < 32; k++) {
        int kk = (k + tx) & 31;   // skew to avoid bank conflicts
        float a[8], bb[8];
        #pragma unroll
        for (int i = 0; i < 8; i++) a[i] = shZ[(r0 + i) * 33 + kk];
        #pragma unroll
        for (int j = 0; j < 8; j++) bb[j] = shZ[(c0 + j) * 33 + kk];
        #pragma unroll
        for (int i = 0; i < 8; i++)
            #pragma unroll
            for (int j = 0; j < 8; j++) acc[i][j] += a[i] * bb[j];
    }

    float lp = 0.f;
    #pragma unroll
    for (int i = 0; i < 8; i++) {
        int r = r0 + i;
        #pragma unroll
        for (int j = 0; j < 8; j++) {
            int cc = c0 + j;
            if (r < cc) {
                float v = acc[i][j];
                int p = r * (2 * Nn - r - 1) / 2 + (cc - r - 1);
                float t = (float)((shM[p >> 5] >> (p & 31)) & 1u);
                lp += t * v - (fmaxf(v, 0.f) + log1pf(__expf(-fabsf(v))));
            }
        }
    }
    float tot = block_reduce(lp);
    if (tid == 0) atomicAdd(&g_acc[0], tot);
}

// ---------------------------------------------------------------------------
__global__ void k_fin(float* out) {
    out[0] = (g_acc[1] - g_acc[0]) * (1.f / (float)Bg);
}

extern "C" void kernel_launch(void* const* d_in, const int* in_sizes, int n_in,
                              void* d_out, int out_size) {
    const float* x   = (const float*)d_in[0];
    const void*  ei  = d_in[1];            // [2,E] int64 or int32 (detected)
    const float* eps = (const float*)d_in[3];
    const float* W1  = (const float*)d_in[4];
    const float* b1  = (const float*)d_in[5];
    const float* Wmu = (const float*)d_in[6];
    const float* bmu = (const float*)d_in[7];
    const float* Wls = (const float*)d_in[8];
    const float* bls = (const float*)d_in[9];

    k_init<<<2048, 256>>>(ei);
    k_scatter<<<Ee / 8, 256>>>(x, ei);
    cudaFuncSetAttribute(k_enc, cudaFuncAttributeMaxDynamicSharedMemorySize, 131072);
    k_enc<<<512, 256, 131072>>>(x, W1, b1, Wmu, bmu, Wls, bls, eps);
    k_dec<<<256, 256>>>();
    k_fin<<<1, 1>>>((float*)d_out);
}